// round 9
// baseline (speedup 1.0000x reference)
#include <cuda_runtime.h>
#include <cuda_fp16.h>
#include <stdint.h>
#include <math.h>

#define BSZ   4096
#define DDIM  512
#define N2    8192
#define MTILE 128
#define NIT   64             // 16 j-tiles (256 cols) * 4 k-chunks (128 K each)

// smem layout (bytes)
#define OFF_A    0           // 4 chunks x 16KB = 65536 (full 128x512 fp8 A)
#define OFF_B    65536       // 3 slots x 32KB (256 rows x 128 Kbytes) = 98304
#define OFF_LJ   163840      // 256 ints = 1024
#define SMEM_TOTAL 164864

#define NSCALE 1.698644f     // sqrt(2/ln2): folds exp(2s)=2^(c*s) scale into reps

// ---------------- device scratch ----------------
__device__ __align__(256) uint8_t g_reps8[(size_t)N2 * DDIM];  // 4 MB e4m3
__device__ int   g_labels[N2];
__device__ float g_pos[N2];
__device__ float g_denomp[8][N2];   // [jh*4 + wx][row]
__device__ int   g_arrive;          // zero-init, reset by last CTA

// ---------------- helpers ----------------
__device__ __forceinline__ uint32_t smem_u32(const void* p) {
    return (uint32_t)__cvta_generic_to_shared(p);
}
__device__ __forceinline__ void cp16(uint32_t s, const void* g) {
    asm volatile("cp.async.cg.shared.global [%0], [%1], 16;"
                 :: "r"(s), "l"(__cvta_generic_to_global(g)) : "memory");
}
#define CP_COMMIT() asm volatile("cp.async.commit_group;" ::: "memory")
#define CP_WAIT(n)  asm volatile("cp.async.wait_group %0;" :: "n"(n) : "memory")

__device__ __forceinline__ uint32_t swz(uint32_t o) { return o ^ ((o >> 3) & 0x70); }

__device__ __forceinline__ void ldsm4(uint32_t* r, uint32_t addr) {
    asm volatile("ldmatrix.sync.aligned.m8n8.x4.shared.b16 {%0,%1,%2,%3}, [%4];"
                 : "=r"(r[0]), "=r"(r[1]), "=r"(r[2]), "=r"(r[3]) : "r"(addr));
}
// e4m3 x e4m3 -> f16 accumulate (acc packed half2 x2)
__device__ __forceinline__ void mma16832q(uint32_t* c, const uint32_t* a, const uint32_t* b) {
    asm volatile("mma.sync.aligned.m16n8k32.row.col.f16.e4m3.e4m3.f16 "
                 "{%0,%1}, {%2,%3,%4,%5}, {%6,%7}, {%0,%1};"
                 : "+r"(c[0]), "+r"(c[1])
                 : "r"(a[0]), "r"(a[1]), "r"(a[2]), "r"(a[3]), "r"(b[0]), "r"(b[1]));
}
__device__ __forceinline__ float ex2(float x) {
    float r; asm("ex2.approx.ftz.f32 %0, %1;" : "=f"(r) : "f"(x)); return r;
}
__device__ __forceinline__ float lg2(float x) {
    float r; asm("lg2.approx.f32 %0, %1;" : "=f"(r) : "f"(x)); return r;
}
__device__ __forceinline__ uint32_t pack_e4m3x4(float a, float b, float c, float d) {
    uint16_t lo, hi;   // cvt packs first src into the upper byte
    asm("cvt.rn.satfinite.e4m3x2.f32 %0, %1, %2;" : "=h"(lo) : "f"(b), "f"(a));
    asm("cvt.rn.satfinite.e4m3x2.f32 %0, %1, %2;" : "=h"(hi) : "f"(d), "f"(c));
    return (uint32_t)lo | ((uint32_t)hi << 16);
}

// ---------------------------------------------------------------------------
// Kernel 1: per-pair normalize -> e4m3 reps scaled by NSCALE; fp32 positives.
// Block 0 additionally decodes labels (robust to int32/int64 target buffer).
// ---------------------------------------------------------------------------
__global__ void normpos_kernel(const float* __restrict__ ei,
                               const float* __restrict__ ej,
                               const int* __restrict__ traw) {
    int i = blockIdx.x;      // 0..4095
    int t = threadIdx.x;     // 128 threads
    float4 vi = reinterpret_cast<const float4*>(ei + (size_t)i * DDIM)[t];
    float4 vj = reinterpret_cast<const float4*>(ej + (size_t)i * DDIM)[t];
    float si = vi.x*vi.x + vi.y*vi.y + vi.z*vi.z + vi.w*vi.w;
    float sj = vj.x*vj.x + vj.y*vj.y + vj.z*vj.z + vj.w*vj.w;
    float dp = vi.x*vj.x + vi.y*vj.y + vi.z*vj.z + vi.w*vj.w;
#pragma unroll
    for (int o = 16; o; o >>= 1) {
        si += __shfl_xor_sync(0xffffffffu, si, o);
        sj += __shfl_xor_sync(0xffffffffu, sj, o);
        dp += __shfl_xor_sync(0xffffffffu, dp, o);
    }
    __shared__ float sm[3][4];
    int w = t >> 5;
    if ((t & 31) == 0) { sm[0][w] = si; sm[1][w] = sj; sm[2][w] = dp; }
    __syncthreads();
    si = sm[0][0] + sm[0][1] + sm[0][2] + sm[0][3];
    sj = sm[1][0] + sm[1][1] + sm[1][2] + sm[1][3];
    dp = sm[2][0] + sm[2][1] + sm[2][2] + sm[2][3];
    float ri = NSCALE / fmaxf(sqrtf(si), 1e-12f);
    float rj = NSCALE / fmaxf(sqrtf(sj), 1e-12f);

    uint32_t* oi = reinterpret_cast<uint32_t*>(g_reps8 + (size_t)i * DDIM);
    uint32_t* oj = reinterpret_cast<uint32_t*>(g_reps8 + (size_t)(i + BSZ) * DDIM);
    oi[t] = pack_e4m3x4(vi.x * ri, vi.y * ri, vi.z * ri, vi.w * ri);
    oj[t] = pack_e4m3x4(vj.x * rj, vj.y * rj, vj.z * rj, vj.w * rj);
    if (t == 0) {
        float pos = (dp / NSCALE / NSCALE) * (ri * rj);  // fp32 exact positive
        g_pos[i] = pos;
        g_pos[i + BSZ] = pos;
    }

    // ---- block 0: decode labels (int32 vs int64 detection) ----
    if (i == 0) {
        __shared__ int odd_nonzero;
        if (t == 0) odd_nonzero = 0;
        __syncthreads();
        int local = 0;
        for (int k = t; k < BSZ / 2; k += 128)
            if (traw[2 * k + 1] != 0) local = 1;
        if (local) atomicOr(&odd_nonzero, 1);
        __syncthreads();
        const bool is64 = (odd_nonzero == 0);
        for (int k = t; k < BSZ; k += 128) {
            int v = is64 ? traw[2 * k] : traw[k];
            g_labels[k] = v;
            g_labels[k + BSZ] = v;
        }
    }
}

// ---------------------------------------------------------------------------
// Kernel 2: fused fp8 mma.sync sim-GEMM + mask + exp + row-sum + finalize.
// grid = 128: (i-tile 0..63) x (j-half 0..1). 512 threads = 16 warps.
// CTA tile per j-step: 128 rows x 256 cols. warp (wy,wx): rows [wy*32,+32),
// cols [wx*64,+64). K chunks of 128 elements (128 B rows); B ring of 3.
// ---------------------------------------------------------------------------
__global__ void __launch_bounds__(512, 1) simloss_kernel(float* __restrict__ out) {
    extern __shared__ __align__(1024) char smem[];
    const uint32_t sb = smem_u32(smem);
    const int tid  = threadIdx.x;
    const int wid  = tid >> 5;
    const int lane = tid & 31;
    const int wx = wid & 3, wy = wid >> 2;
    const int iBase  = (blockIdx.x >> 1) * MTILE;
    const int jh     = blockIdx.x & 1;
    const int jStart = jh * 4096;

    int* ljS = reinterpret_cast<int*>(smem + OFF_LJ);

    // positive-pair j-tile index within this half (256-col tiles), or -1
    const int posCol = (iBase < BSZ) ? iBase + BSZ : iBase - BSZ;
    const int sjt = (posCol >= jStart && posCol < jStart + 4096)
                        ? ((posCol - jStart) >> 8) : -1;
    const int pdelta = (iBase < BSZ) ? BSZ : -BSZ;

    // ---- prologue: G0 = A(4 chunks) + B chunk0; G1 = B chunk1 ----
#pragma unroll
    for (int x = 0; x < 8; ++x) {
        int u = tid + x * 512;                  // 16B units of A (4096 total)
        int ch = u >> 10, v = u & 1023;
        int rowb = v >> 3, c16 = v & 7;
        cp16(sb + OFF_A + ch * 16384 + swz(rowb * 128 + c16 * 16),
             g_reps8 + (size_t)(iBase + rowb) * DDIM + ch * 128 + c16 * 16);
    }
#pragma unroll
    for (int x = 0; x < 4; ++x) {               // B iter0: jt0, ch0
        int u = tid + x * 512;                  // 0..2047
        int rowb = u >> 3, c16 = u & 7;
        cp16(sb + OFF_B + swz(rowb * 128 + c16 * 16),
             g_reps8 + (size_t)(jStart + rowb) * DDIM + c16 * 16);
    }
    CP_COMMIT();
#pragma unroll
    for (int x = 0; x < 4; ++x) {               // B iter1: jt0, ch1
        int u = tid + x * 512;
        int rowb = u >> 3, c16 = u & 7;
        cp16(sb + OFF_B + 32768 + swz(rowb * 128 + c16 * 16),
             g_reps8 + (size_t)(jStart + rowb) * DDIM + 128 + c16 * 16);
    }
    CP_COMMIT();

    // fragment address pieces (byte offsets; same geometry as f16 k16 path)
    const int arow  = lane & 15;
    const int acolb = (lane >> 4) * 16;
    const int brow  = (lane & 7) + ((lane >> 4) & 1) * 8;
    const int bcolb = ((lane >> 3) & 1) * 16;
    uint32_t aOff[2], bOff[4];
#pragma unroll
    for (int mf = 0; mf < 2; ++mf)
        aOff[mf] = (wy * 32 + mf * 16 + arow) * 128 + acolb;
#pragma unroll
    for (int nf2 = 0; nf2 < 4; ++nf2)
        bOff[nf2] = (wx * 64 + nf2 * 16 + brow) * 128 + bcolb;

    // row identity
    const int q = lane >> 2;
    const int t4 = lane & 3;
    int l0[2], l1[2];
#pragma unroll
    for (int mf = 0; mf < 2; ++mf) {
        l0[mf] = g_labels[iBase + wy * 32 + mf * 16 + q];
        l1[mf] = g_labels[iBase + wy * 32 + mf * 16 + q + 8];
    }

    uint32_t acc[2][8][2];     // f16x2 accumulators
    float rs[2][2] = {};       // row sums: [mf][rowhalf]
    int buf = 0;               // ring slot (mod 3)

    for (int i = 0; i < NIT; ++i) {
        const int jt = i >> 2;
        const int ch = i & 3;

        if (i < NIT - 1) CP_WAIT(1); else CP_WAIT(0);
        __syncthreads();

        if (ch == 0 && tid < 256)
            ljS[tid] = g_labels[jStart + jt * 256 + tid];

        // prefetch chunk for iteration i+2 into ring slot (buf+2)%3
        if (i + 2 < NIT) {
            const int fb = (buf + 2 >= 3) ? buf - 1 : buf + 2;
            const int njt = (i + 2) >> 2, nch = (i + 2) & 3;
            const uint8_t* gb =
                g_reps8 + (size_t)(jStart + njt * 256) * DDIM + nch * 128;
            uint32_t sB = sb + OFF_B + fb * 32768;
#pragma unroll
            for (int x = 0; x < 4; ++x) {
                int u = tid + x * 512;
                int rowb = u >> 3, c16 = u & 7;
                cp16(sB + swz(rowb * 128 + c16 * 16), gb + (size_t)rowb * DDIM + c16 * 16);
            }
            CP_COMMIT();
        }

        if (ch == 0) {
#pragma unroll
            for (int mf = 0; mf < 2; ++mf)
#pragma unroll
                for (int nf = 0; nf < 8; ++nf)
                    acc[mf][nf][0] = acc[mf][nf][1] = 0u;
        }

        // ---- compute one 128-K chunk over 256 cols ----
        {
            const uint32_t sA = sb + OFF_A + ch * 16384;
            const uint32_t sB = sb + OFF_B + buf * 32768;
#pragma unroll
            for (int ks = 0; ks < 4; ++ks) {    // 32 K-bytes per step
                uint32_t a[2][4], b[4][4];
#pragma unroll
                for (int mf = 0; mf < 2; ++mf) ldsm4(a[mf], sA + swz(aOff[mf] + ks * 32));
#pragma unroll
                for (int nf2 = 0; nf2 < 4; ++nf2) ldsm4(b[nf2], sB + swz(bOff[nf2] + ks * 32));
#pragma unroll
                for (int mf = 0; mf < 2; ++mf)
#pragma unroll
                    for (int nf = 0; nf < 8; ++nf)
                        mma16832q(acc[mf][nf], a[mf], &b[nf >> 1][(nf & 1) * 2]);
            }
        }

        // ---- epilogue at tile end ----
        if (ch == 3) {
            const bool special = (jt == sjt);
            const int colBase = jStart + jt * 256;
#pragma unroll
            for (int mf = 0; mf < 2; ++mf) {
                const int gi0 = iBase + wy * 32 + mf * 16 + q;
                const int la = l0[mf], lb = l1[mf];
                float s0 = 0.f, s1 = 0.f;
                if (!special) {
#pragma unroll
                    for (int nf = 0; nf < 8; ++nf) {
                        const int c0 = wx * 64 + nf * 8 + t4 * 2;
                        const int lj0 = ljS[c0], lj1 = ljS[c0 + 1];
                        float2 v0 = __half22float2(*(__half2*)&acc[mf][nf][0]);
                        float2 v1 = __half22float2(*(__half2*)&acc[mf][nf][1]);
                        float e00 = ex2(v0.x), e01 = ex2(v0.y);
                        float e10 = ex2(v1.x), e11 = ex2(v1.y);
                        if (la != lj0) s0 += e00;
                        if (la != lj1) s0 += e01;
                        if (lb != lj0) s1 += e10;
                        if (lb != lj1) s1 += e11;
                    }
                } else {
                    const int pc0 = gi0 + pdelta, pc1 = gi0 + 8 + pdelta;
#pragma unroll
                    for (int nf = 0; nf < 8; ++nf) {
                        const int c0 = wx * 64 + nf * 8 + t4 * 2;
                        const int lj0 = ljS[c0], lj1 = ljS[c0 + 1];
                        const int gj0 = colBase + c0, gj1 = gj0 + 1;
                        float2 v0 = __half22float2(*(__half2*)&acc[mf][nf][0]);
                        float2 v1 = __half22float2(*(__half2*)&acc[mf][nf][1]);
                        float e00 = ex2(v0.x), e01 = ex2(v0.y);
                        float e10 = ex2(v1.x), e11 = ex2(v1.y);
                        if (la != lj0 || gj0 == pc0) {} else e00 = 0.f;
                        if (la != lj1 || gj1 == pc0) {} else e01 = 0.f;
                        if (lb != lj0 || gj0 == pc1) {} else e10 = 0.f;
                        if (lb != lj1 || gj1 == pc1) {} else e11 = 0.f;
                        s0 += e00 + e01;
                        s1 += e10 + e11;
                    }
                }
                rs[mf][0] += s0;
                rs[mf][1] += s1;
            }
        }
        buf = (buf == 2) ? 0 : buf + 1;
    }

    // reduce row sums across the 4 lanes of each quad-column group
#pragma unroll
    for (int mf = 0; mf < 2; ++mf) {
        float r0 = rs[mf][0], r1 = rs[mf][1];
        r0 += __shfl_xor_sync(0xffffffffu, r0, 1);
        r0 += __shfl_xor_sync(0xffffffffu, r0, 2);
        r1 += __shfl_xor_sync(0xffffffffu, r1, 1);
        r1 += __shfl_xor_sync(0xffffffffu, r1, 2);
        if (t4 == 0) {
            int row = iBase + wy * 32 + mf * 16 + q;
            g_denomp[jh * 4 + wx][row] = r0;
            g_denomp[jh * 4 + wx][row + 8] = r1;
        }
    }

    // ---- last CTA computes the final loss ----
    __threadfence();
    __shared__ int amLast;
    if (tid == 0) amLast = (atomicAdd(&g_arrive, 1) == gridDim.x - 1);
    __syncthreads();
    if (amLast) {
        __threadfence();
        float s = 0.0f;
        for (int i = tid; i < N2; i += 512) {
            float den = 0.f;
#pragma unroll
            for (int p = 0; p < 8; ++p) den += g_denomp[p][i];
            s += lg2(den + 1e-7f) * 0.6931471805599453f - 2.0f * g_pos[i];
        }
        float* red = reinterpret_cast<float*>(smem + OFF_B);
        red[tid] = s;
        __syncthreads();
        for (int st = 256; st; st >>= 1) {
            if (tid < st) red[tid] += red[tid + st];
            __syncthreads();
        }
        if (tid == 0) {
            out[0] = red[0] / (float)N2;
            g_arrive = 0;
        }
    }
}

// ---------------------------------------------------------------------------
extern "C" void kernel_launch(void* const* d_in, const int* in_sizes, int n_in,
                              void* d_out, int out_size) {
    const float* emb_i = (const float*)d_in[0];
    const float* emb_j = (const float*)d_in[1];
    const int*   traw  = (const int*)d_in[2];
    float* out = (float*)d_out;

    cudaFuncSetAttribute(simloss_kernel,
                         cudaFuncAttributeMaxDynamicSharedMemorySize, SMEM_TOTAL);

    normpos_kernel<<<BSZ, 128>>>(emb_i, emb_j, traw);
    simloss_kernel<<<128, 512, SMEM_TOTAL>>>(out);
}